// round 13
// baseline (speedup 1.0000x reference)
#include <cuda_runtime.h>
#include <cuda_bf16.h>
#include <cstdint>

#define N_NODES 50000
#define N_EDGES 600000
#define B_GR    4096
#define DIM     128
#define L_IT    3
#define EPSBN   1e-5f

// ---------------- device scratch (static globals: allocation-free) -------------
__device__ int   g_deg[2 * N_NODES];
__device__ int   g_offs[2 * (N_NODES + 1)];
__device__ int   g_cursor[2 * N_NODES];
__device__ int   g_csr[2 * N_EDGES];
__device__ float g_agg[2][N_NODES * DIM];
__device__ float g_xbuf[2][2][N_NODES * DIM];   // [pingpong][graph]
__device__ float g_pool[2][B_GR * DIM];
// W split into bf16 b0/b1 planes, n-major [n][k] (k: 0-127 Wl, 128-255 Wr)
__device__ __nv_bfloat16 g_wb[L_IT][2][128][256];

// pack two floats into a bf16x2 word (round-to-nearest)
__device__ __forceinline__ uint32_t pack_bf2(float lo, float hi) {
    uint16_t l = __bfloat16_as_ushort(__float2bfloat16(lo));
    uint16_t h = __bfloat16_as_ushort(__float2bfloat16(hi));
    return (uint32_t)l | ((uint32_t)h << 16);
}
__device__ __forceinline__ float bf_hi_part(float v) {
    // value of bf16(v) as float
    return __bfloat162float(__float2bfloat16(v));
}

// ---------------- zero deg + pool ------------------------------------------------
__global__ void zero_kernel() {
    int i = blockIdx.x * blockDim.x + threadIdx.x;
    int stride = gridDim.x * blockDim.x;
    for (int j = i; j < 2 * N_NODES; j += stride) g_deg[j] = 0;
    float* p = &g_pool[0][0];
    for (int j = i; j < 2 * B_GR * DIM; j += stride) p[j] = 0.0f;
}

// ---------------- W split into bf16 b0/b1 planes ---------------------------------
__global__ void wsplit_kernel(const float* __restrict__ Wl, const float* __restrict__ Wr) {
    int idx = blockIdx.x * blockDim.x + threadIdx.x;   // [l][n][k]
    if (idx >= L_IT * 128 * 256) return;
    int k = idx & 255;
    int n = (idx >> 8) & 127;
    int l = idx >> 15;
    float v = (k < 128) ? Wl[(l * 128 + k) * 128 + n]
                        : Wr[(l * 128 + (k - 128)) * 128 + n];
    __nv_bfloat16 b0 = __float2bfloat16(v);
    __nv_bfloat16 b1 = __float2bfloat16(v - __bfloat162float(b0));
    g_wb[l][0][n][k] = b0;
    g_wb[l][1][n][k] = b1;
}

// ---------------- histogram of in-degrees ---------------------------------------
__global__ void hist_kernel(const int* __restrict__ e1, const int* __restrict__ e2) {
    int g = blockIdx.y;
    const int* dst = (g ? e2 : e1) + N_EDGES;
    int i = blockIdx.x * blockDim.x + threadIdx.x;
    if (i < N_EDGES) atomicAdd(&g_deg[g * N_NODES + dst[i]], 1);
}

// ---------------- single-block exclusive scan per graph (writes offs + cursor) ---
__global__ void scan_kernel() {
    int g = blockIdx.x;
    const int* deg = g_deg + g * N_NODES;
    int* offs = g_offs + g * (N_NODES + 1);
    int* cur  = g_cursor + g * N_NODES;
    __shared__ int warpsum[32];
    __shared__ int s_running;
    __shared__ int s_chunk;
    if (threadIdx.x == 0) s_running = 0;
    __syncthreads();
    int lane = threadIdx.x & 31, w = threadIdx.x >> 5;
    for (int base = 0; base < N_NODES; base += 1024) {
        int i = base + threadIdx.x;
        int v = (i < N_NODES) ? deg[i] : 0;
        int s = v;
        #pragma unroll
        for (int o = 1; o < 32; o <<= 1) {
            int t = __shfl_up_sync(0xffffffffu, s, o);
            if (lane >= o) s += t;
        }
        if (lane == 31) warpsum[w] = s;
        __syncthreads();
        if (w == 0) {
            int ws = warpsum[lane];
            int ss = ws;
            #pragma unroll
            for (int o = 1; o < 32; o <<= 1) {
                int t = __shfl_up_sync(0xffffffffu, ss, o);
                if (lane >= o) ss += t;
            }
            if (lane == 31) s_chunk = ss;
            warpsum[lane] = ss - ws;
        }
        __syncthreads();
        int excl = s_running + warpsum[w] + (s - v);
        if (i < N_NODES) { offs[i] = excl; cur[i] = excl; }
        __syncthreads();
        if (threadIdx.x == 0) s_running += s_chunk;
        __syncthreads();
    }
    if (threadIdx.x == 0) offs[N_NODES] = s_running;
}

// ---------------- scatter edges into CSR ----------------------------------------
__global__ void scatter_kernel(const int* __restrict__ e1, const int* __restrict__ e2) {
    int g = blockIdx.y;
    const int* ei = g ? e2 : e1;
    int i = blockIdx.x * blockDim.x + threadIdx.x;
    if (i < N_EDGES) {
        int s = ei[i];
        int d = ei[N_EDGES + i];
        int p = atomicAdd(&g_cursor[g * N_NODES + d], 1);
        g_csr[g * N_EDGES + p] = s;
    }
}

// ---------------- gather aggregation: agg[n] = mean of x[src] -------------------
__global__ void agg_kernel(const float* __restrict__ x0, const float* __restrict__ x1,
                           int in_sel) {
    int g = blockIdx.y;
    int warp = (blockIdx.x * blockDim.x + threadIdx.x) >> 5;
    int lane = threadIdx.x & 31;
    if (warp >= N_NODES) return;
    const float* xp = (in_sel < 0) ? (g ? x1 : x0) : g_xbuf[in_sel][g];
    const float4* x = (const float4*)xp;
    const int* offs = g_offs + g * (N_NODES + 1);
    const int* csr = g_csr + g * N_EDGES;
    int s = offs[warp], e = offs[warp + 1];
    float4 acc = make_float4(0.f, 0.f, 0.f, 0.f);
    for (int j = s; j < e; j++) {
        int src = csr[j];
        float4 t = x[src * 32 + lane];
        acc.x += t.x; acc.y += t.y; acc.z += t.z; acc.w += t.w;
    }
    int d = e - s; if (d < 1) d = 1;
    float inv = 1.0f / (float)d;
    acc.x *= inv; acc.y *= inv; acc.z *= inv; acc.w *= inv;
    ((float4*)g_agg[g])[warp * 32 + lane] = acc;
}

// ---------------- bf16x3 mma.sync GEMM -------------------------------------------
// C[128 x 128] = A[128 x 256] @ W[256 x 128], A = [agg | x].
// A split into bf16 hi/lo planes at chunk-store time (stride 40 bf16 -> 32 banks).
// W pre-split (wsplit) and loaded to smem once per block (stride 264 -> 32 banks).
// 3 mma terms per k16: Ahi*Bhi + Alo*Bhi + Ahi*Blo (~2^-16 accuracy).
#define SW_ST 264
#define SA_ST 40
#define W_PLANE (128 * SW_ST * 2)            // bytes per W plane
#define A_PLANE (128 * SA_ST * 2)            // bytes per A plane
#define A_BASE  (2 * W_PLANE)
#define A_BUF   (2 * A_PLANE)                // hi + lo
#define EX_BASE (A_BASE + 2 * A_BUF)
#define GSMEM   (EX_BASE + 1024)

__device__ __forceinline__ void mma_bf16(float c[4], const uint32_t a[4],
                                         uint32_t b0, uint32_t b1) {
    asm volatile(
        "mma.sync.aligned.m16n8k16.row.col.f32.bf16.bf16.f32 "
        "{%0,%1,%2,%3},{%4,%5,%6,%7},{%8,%9},{%0,%1,%2,%3};"
        : "+f"(c[0]), "+f"(c[1]), "+f"(c[2]), "+f"(c[3])
        : "r"(a[0]), "r"(a[1]), "r"(a[2]), "r"(a[3]), "r"(b0), "r"(b1));
}

__global__ void __launch_bounds__(256)
gemm_kernel(const float* __restrict__ x0, const float* __restrict__ x1,
            const float* __restrict__ bl,
            const float* __restrict__ gam, const float* __restrict__ bet,
            const float* __restrict__ mean, const float* __restrict__ var,
            int layer, int in_sel, int out_sel) {
    int g = blockIdx.y;
    const float* x = (in_sel < 0) ? (g ? x1 : x0) : g_xbuf[in_sel][g];
    const float* agg = g_agg[g];
    float* outp = g_xbuf[out_sel][g];

    extern __shared__ __align__(16) char sm[];
    char* sW0 = sm;                 // W b0 plane [128 n][264 k] bf16
    char* sW1 = sm + W_PLANE;       // W b1 plane
    float* ssc = (float*)(sm + EX_BASE);
    float* ssh = ssc + 128;

    int tid = threadIdx.x;
    int lane = tid & 31, wid = tid >> 5;
    int gp = lane >> 2, tig = lane & 3;
    int warp_m = (wid & 3) * 32;
    int warp_n = (wid >> 2) * 64;
    int row0 = blockIdx.x * 128;

    if (tid < 128) {
        float s = gam[tid] * rsqrtf(var[tid] + EPSBN);
        ssc[tid] = s;
        ssh[tid] = (bl[tid] - mean[tid]) * s + bet[tid];
    }

    // Load W planes (64KB each) into smem with stride 264 bf16 (= 528B rows)
    {
        const uint4* w0 = (const uint4*)&g_wb[layer][0][0][0];
        const uint4* w1 = (const uint4*)&g_wb[layer][1][0][0];
        #pragma unroll
        for (int t = 0; t < 16; t++) {
            int i = tid + t * 256;          // i in [0, 4096): [n][32 uint4]
            int n = i >> 5, c16 = i & 31;
            *(uint4*)(sW0 + n * (SW_ST * 2) + c16 * 16) = w0[i];
            *(uint4*)(sW1 + n * (SW_ST * 2) + c16 * 16) = w1[i];
        }
    }

    // A chunk staging: 128 rows x 32 k = 1024 float4, 4 per thread
    float4 stage[4];
    auto ldg_chunk = [&](int c) {
        const float* src = (c < 4) ? agg : x;
        int coff = (c & 3) * 32;
        #pragma unroll
        for (int t = 0; t < 4; t++) {
            int i = tid + t * 256;
            int r = i >> 3, c4 = i & 7;
            float4 v = make_float4(0.f, 0.f, 0.f, 0.f);
            int row = row0 + r;
            if (row < N_NODES) v = *(const float4*)(src + row * 128 + coff + c4 * 4);
            stage[t] = v;
        }
    };
    auto sts_chunk = [&](int buf) {
        char* hi = sm + A_BASE + buf * A_BUF;
        char* lo = hi + A_PLANE;
        #pragma unroll
        for (int t = 0; t < 4; t++) {
            int i = tid + t * 256;
            int r = i >> 3, c4 = i & 7;
            float4 v = stage[t];
            uint32_t h01 = pack_bf2(v.x, v.y);
            uint32_t h23 = pack_bf2(v.z, v.w);
            uint32_t l01 = pack_bf2(v.x - bf_hi_part(v.x), v.y - bf_hi_part(v.y));
            uint32_t l23 = pack_bf2(v.z - bf_hi_part(v.z), v.w - bf_hi_part(v.w));
            uint32_t off = r * (SA_ST * 2) + c4 * 8;
            *(uint2*)(hi + off) = make_uint2(h01, h23);
            *(uint2*)(lo + off) = make_uint2(l01, l23);
        }
    };

    ldg_chunk(0);
    sts_chunk(0);
    __syncthreads();

    float acc[2][8][4];
    #pragma unroll
    for (int mt = 0; mt < 2; mt++)
        #pragma unroll
        for (int n8 = 0; n8 < 8; n8++)
            #pragma unroll
            for (int j = 0; j < 4; j++) acc[mt][n8][j] = 0.f;

    for (int c = 0; c < 8; c++) {
        if (c + 1 < 8) ldg_chunk(c + 1);
        int buf = c & 1;
        const char* Ahi = sm + A_BASE + buf * A_BUF;
        const char* Alo = Ahi + A_PLANE;
        #pragma unroll
        for (int k16 = 0; k16 < 2; k16++) {
            int kloc = k16 * 16 + tig * 2;                 // bf16 units within chunk
            uint32_t ah[2][4], al[2][4];
            #pragma unroll
            for (int mt = 0; mt < 2; mt++) {
                int r = warp_m + mt * 16 + gp;
                uint32_t o00 = r * (SA_ST * 2) + kloc * 2;
                uint32_t o10 = o00 + 8 * (SA_ST * 2);
                ah[mt][0] = *(const uint32_t*)(Ahi + o00);
                ah[mt][1] = *(const uint32_t*)(Ahi + o10);
                ah[mt][2] = *(const uint32_t*)(Ahi + o00 + 16);
                ah[mt][3] = *(const uint32_t*)(Ahi + o10 + 16);
                al[mt][0] = *(const uint32_t*)(Alo + o00);
                al[mt][1] = *(const uint32_t*)(Alo + o10);
                al[mt][2] = *(const uint32_t*)(Alo + o00 + 16);
                al[mt][3] = *(const uint32_t*)(Alo + o10 + 16);
            }
            int kg = c * 32 + k16 * 16 + tig * 2;          // global k, bf16 units
            #pragma unroll
            for (int n8 = 0; n8 < 8; n8++) {
                int n = warp_n + n8 * 8 + gp;
                uint32_t wo = n * (SW_ST * 2) + kg * 2;
                uint32_t bh0 = *(const uint32_t*)(sW0 + wo);
                uint32_t bh1 = *(const uint32_t*)(sW0 + wo + 16);
                uint32_t bl0 = *(const uint32_t*)(sW1 + wo);
                uint32_t bl1 = *(const uint32_t*)(sW1 + wo + 16);
                #pragma unroll
                for (int mt = 0; mt < 2; mt++) {
                    mma_bf16(acc[mt][n8], ah[mt], bh0, bh1);
                    mma_bf16(acc[mt][n8], al[mt], bh0, bh1);
                    mma_bf16(acc[mt][n8], ah[mt], bl0, bl1);
                }
            }
        }
        __syncthreads();
        if (c + 1 < 8) {
            sts_chunk(buf ^ 1);
            __syncthreads();
        }
    }

    // epilogue: BN (eval, bias folded) + relu
    #pragma unroll
    for (int mt = 0; mt < 2; mt++) {
        int ra = row0 + warp_m + mt * 16 + gp;
        int rb = ra + 8;
        #pragma unroll
        for (int n8 = 0; n8 < 8; n8++) {
            int col = warp_n + n8 * 8 + 2 * tig;
            float s0 = ssc[col], s1 = ssc[col + 1];
            float h0 = ssh[col], h1 = ssh[col + 1];
            if (ra < N_NODES) {
                float2 o;
                o.x = fmaxf(acc[mt][n8][0] * s0 + h0, 0.f);
                o.y = fmaxf(acc[mt][n8][1] * s1 + h1, 0.f);
                *(float2*)&outp[ra * 128 + col] = o;
            }
            if (rb < N_NODES) {
                float2 o;
                o.x = fmaxf(acc[mt][n8][2] * s0 + h0, 0.f);
                o.y = fmaxf(acc[mt][n8][3] * s1 + h1, 0.f);
                *(float2*)&outp[rb * 128 + col] = o;
            }
        }
    }
}

// ---------------- global add pool ------------------------------------------------
__global__ void pool_kernel(const int* __restrict__ batch0, const int* __restrict__ batch1,
                            int in_sel) {
    int g = blockIdx.y;
    int warp = (blockIdx.x * blockDim.x + threadIdx.x) >> 5;
    int lane = threadIdx.x & 31;
    if (warp >= N_NODES) return;
    const float* xf = g_xbuf[in_sel][g];
    int b = (g ? batch1 : batch0)[warp];
    float4 v = ((const float4*)xf)[warp * 32 + lane];
    float* p = &g_pool[g][b * 128 + lane * 4];
    atomicAdd(p + 0, v.x);
    atomicAdd(p + 1, v.y);
    atomicAdd(p + 2, v.z);
    atomicAdd(p + 3, v.w);
}

// ---------------- final MLP: [B,384]@[384,128] -> relu -> @[128,1] ---------------
__global__ void __launch_bounds__(128)
mlp_kernel(const int* __restrict__ rel, const float* __restrict__ kge,
           const float* __restrict__ W1, const float* __restrict__ b1,
           const float* __restrict__ W2, const float* __restrict__ b2,
           float* __restrict__ out) {
    __shared__ float zsm[8][384];
    __shared__ float red[8][4];
    int tid = threadIdx.x;
    int b0 = blockIdx.x * 8;
    #pragma unroll
    for (int j = 0; j < 8; j++) {
        int b = b0 + j;
        zsm[j][tid]       = g_pool[0][b * 128 + tid];
        zsm[j][128 + tid] = g_pool[1][b * 128 + tid];
        zsm[j][256 + tid] = kge[rel[b] * 128 + tid];
    }
    __syncthreads();
    float acc[8];
    float bias = b1[tid];
    #pragma unroll
    for (int j = 0; j < 8; j++) acc[j] = bias;
    for (int k = 0; k < 384; k++) {
        float w = W1[k * 128 + tid];
        #pragma unroll
        for (int j = 0; j < 8; j++) acc[j] += zsm[j][k] * w;
    }
    float w2 = W2[tid];
    #pragma unroll
    for (int j = 0; j < 8; j++) {
        float h = fmaxf(acc[j], 0.f) * w2;
        #pragma unroll
        for (int o = 16; o > 0; o >>= 1) h += __shfl_down_sync(0xffffffffu, h, o);
        if ((tid & 31) == 0) red[j][tid >> 5] = h;
    }
    __syncthreads();
    if (tid < 8)
        out[b0 + tid] = red[tid][0] + red[tid][1] + red[tid][2] + red[tid][3] + b2[0];
}

// ---------------- host launcher ---------------------------------------------------
extern "C" void kernel_launch(void* const* d_in, const int* in_sizes, int n_in,
                              void* d_out, int out_size) {
    int ix1 = 0, ie1, ib1, ix2, ie2, ib2;
    if (in_sizes[1] == 2 * N_EDGES) {           // reference-signature order
        ie1 = 1; ib1 = 2; ix2 = 3; ie2 = 4; ib2 = 5;
    } else {                                    // setup_inputs dict order
        ix2 = 1; ie1 = 2; ie2 = 3; ib1 = 4; ib2 = 5;
    }
    const float* x1     = (const float*)d_in[ix1];
    const float* x2     = (const float*)d_in[ix2];
    const int*   e1     = (const int*)d_in[ie1];
    const int*   e2     = (const int*)d_in[ie2];
    const int*   batch1 = (const int*)d_in[ib1];
    const int*   batch2 = (const int*)d_in[ib2];
    const int*   rel    = (const int*)d_in[6];
    const float* Wl     = (const float*)d_in[7];
    const float* bl     = (const float*)d_in[8];
    const float* Wr     = (const float*)d_in[9];
    const float* gam    = (const float*)d_in[10];
    const float* bet    = (const float*)d_in[11];
    const float* mean   = (const float*)d_in[12];
    const float* var    = (const float*)d_in[13];
    const float* kge    = (const float*)d_in[14];
    const float* W1     = (const float*)d_in[15];
    const float* b1     = (const float*)d_in[16];
    const float* W2     = (const float*)d_in[17];
    const float* b2     = (const float*)d_in[18];
    float* out = (float*)d_out;

    static int attr_done = 0;
    if (!attr_done) {
        cudaFuncSetAttribute(gemm_kernel, cudaFuncAttributeMaxDynamicSharedMemorySize,
                             GSMEM);
        attr_done = 1;
    }

    zero_kernel<<<256, 256>>>();
    wsplit_kernel<<<(L_IT * 128 * 256 + 255) / 256, 256>>>(Wl, Wr);

    dim3 gE((N_EDGES + 255) / 256, 2);
    hist_kernel<<<gE, 256>>>(e1, e2);
    scan_kernel<<<2, 1024>>>();
    scatter_kernel<<<gE, 256>>>(e1, e2);

    dim3 gWarp((N_NODES + 7) / 8, 2);
    dim3 gGemm((N_NODES + 127) / 128, 2);

    int in_sel = -1;
    int out_sel = 0;
    for (int l = 0; l < L_IT; l++) {
        agg_kernel<<<gWarp, 256>>>(x1, x2, in_sel);
        gemm_kernel<<<gGemm, 256, GSMEM>>>(x1, x2,
                                           bl + l * DIM,
                                           gam + l * DIM, bet + l * DIM,
                                           mean + l * DIM, var + l * DIM,
                                           l, in_sel, out_sel);
        in_sel = out_sel;
        out_sel ^= 1;
    }

    pool_kernel<<<gWarp, 256>>>(batch1, batch2, in_sel);
    mlp_kernel<<<B_GR / 8, 128>>>(rel, kge, W1, b1, W2, b2, out);
    (void)n_in; (void)out_size;
}

// round 14
// speedup vs baseline: 1.0600x; 1.0600x over previous
#include <cuda_runtime.h>
#include <cuda_bf16.h>
#include <cstdint>

#define N_NODES 50000
#define N_EDGES 600000
#define B_GR    4096
#define DIM     128
#define L_IT    3
#define EPSBN   1e-5f

#define SCAN_NB 25
#define SCAN_CH 2000

// ---------------- device scratch (static globals: allocation-free) -------------
__device__ int   g_deg[2 * N_NODES];
__device__ int   g_offs[2 * (N_NODES + 1)];
__device__ int   g_cursor[2 * N_NODES];
__device__ int   g_csr[2 * N_EDGES];
__device__ int   g_part[2][SCAN_NB];
__device__ float g_agg[2][N_NODES * DIM];
__device__ float g_xbuf[2][2][N_NODES * DIM];   // [pingpong][graph]
__device__ float g_pool[2][B_GR * DIM];
// W split into bf16 b0/b1 planes, n-major [n][k] (k: 0-127 Wl, 128-255 Wr)
__device__ __nv_bfloat16 g_wb[L_IT][2][128][256];

// pack two floats into a bf16x2 word (round-to-nearest)
__device__ __forceinline__ uint32_t pack_bf2(float lo, float hi) {
    uint16_t l = __bfloat16_as_ushort(__float2bfloat16(lo));
    uint16_t h = __bfloat16_as_ushort(__float2bfloat16(hi));
    return (uint32_t)l | ((uint32_t)h << 16);
}
__device__ __forceinline__ float bf_hi_part(float v) {
    return __bfloat162float(__float2bfloat16(v));
}

// ---------------- zero deg + pool ------------------------------------------------
__global__ void zero_kernel() {
    int i = blockIdx.x * blockDim.x + threadIdx.x;
    int stride = gridDim.x * blockDim.x;
    for (int j = i; j < 2 * N_NODES; j += stride) g_deg[j] = 0;
    float* p = &g_pool[0][0];
    for (int j = i; j < 2 * B_GR * DIM; j += stride) p[j] = 0.0f;
}

// ---------------- W split into bf16 b0/b1 planes ---------------------------------
__global__ void wsplit_kernel(const float* __restrict__ Wl, const float* __restrict__ Wr) {
    int idx = blockIdx.x * blockDim.x + threadIdx.x;   // [l][n][k]
    if (idx >= L_IT * 128 * 256) return;
    int k = idx & 255;
    int n = (idx >> 8) & 127;
    int l = idx >> 15;
    float v = (k < 128) ? Wl[(l * 128 + k) * 128 + n]
                        : Wr[(l * 128 + (k - 128)) * 128 + n];
    __nv_bfloat16 b0 = __float2bfloat16(v);
    __nv_bfloat16 b1 = __float2bfloat16(v - __bfloat162float(b0));
    g_wb[l][0][n][k] = b0;
    g_wb[l][1][n][k] = b1;
}

// ---------------- histogram of in-degrees ---------------------------------------
__global__ void hist_kernel(const int* __restrict__ ei, int g) {
    const int* dst = ei + N_EDGES;
    int i = blockIdx.x * blockDim.x + threadIdx.x;
    if (i < N_EDGES) atomicAdd(&g_deg[g * N_NODES + dst[i]], 1);
}

// ---------------- 3-phase multi-block scan ---------------------------------------
__global__ void __launch_bounds__(1024) scan1_kernel(int g) {
    int b = blockIdx.x;
    const int* deg = g_deg + g * N_NODES + b * SCAN_CH;
    int* offs = g_offs + g * (N_NODES + 1) + b * SCAN_CH;
    int tid = threadIdx.x;
    int i0 = 2 * tid;
    int v0 = (i0 < SCAN_CH) ? deg[i0] : 0;
    int v1 = (i0 + 1 < SCAN_CH) ? deg[i0 + 1] : 0;
    int ts = v0 + v1;
    __shared__ int wsum[32];
    int lane = tid & 31, w = tid >> 5;
    int s = ts;
    #pragma unroll
    for (int o = 1; o < 32; o <<= 1) {
        int t = __shfl_up_sync(0xffffffffu, s, o);
        if (lane >= o) s += t;
    }
    if (lane == 31) wsum[w] = s;
    __syncthreads();
    if (w == 0) {
        int ws = wsum[lane];
        int ss = ws;
        #pragma unroll
        for (int o = 1; o < 32; o <<= 1) {
            int t = __shfl_up_sync(0xffffffffu, ss, o);
            if (lane >= o) ss += t;
        }
        wsum[lane] = ss - ws;
        if (lane == 31) g_part[g][b == 0 ? 0 : b] = 0;   // placeholder, overwritten below
        if (lane == 31 && b >= 0) g_part[g][b] = ss;     // block total
    }
    __syncthreads();
    int excl = wsum[w] + (s - ts);
    if (i0 < SCAN_CH) offs[i0] = excl;
    if (i0 + 1 < SCAN_CH) offs[i0 + 1] = excl + v0;
}

__global__ void scan2_kernel(int g) {
    int lane = threadIdx.x;
    int v = (lane < SCAN_NB) ? g_part[g][lane] : 0;
    int s = v;
    #pragma unroll
    for (int o = 1; o < 32; o <<= 1) {
        int t = __shfl_up_sync(0xffffffffu, s, o);
        if (lane >= o) s += t;
    }
    if (lane < SCAN_NB) g_part[g][lane] = s - v;   // exclusive block offset
    if (lane == 31) g_offs[g * (N_NODES + 1) + N_NODES] = s;  // grand total
}

__global__ void __launch_bounds__(1024) scan3_kernel(int g) {
    int b = blockIdx.x;
    int add = g_part[g][b];
    int obase = g * (N_NODES + 1) + b * SCAN_CH;
    int cbase = g * N_NODES + b * SCAN_CH;
    int i0 = 2 * threadIdx.x;
    if (i0 < SCAN_CH) {
        int v = g_offs[obase + i0] + add;
        g_offs[obase + i0] = v;
        g_cursor[cbase + i0] = v;
    }
    if (i0 + 1 < SCAN_CH) {
        int v = g_offs[obase + i0 + 1] + add;
        g_offs[obase + i0 + 1] = v;
        g_cursor[cbase + i0 + 1] = v;
    }
}

// ---------------- scatter edges into CSR ----------------------------------------
__global__ void scatter_kernel(const int* __restrict__ ei, int g) {
    int i = blockIdx.x * blockDim.x + threadIdx.x;
    if (i < N_EDGES) {
        int s = ei[i];
        int d = ei[N_EDGES + i];
        int p = atomicAdd(&g_cursor[g * N_NODES + d], 1);
        g_csr[g * N_EDGES + p] = s;
    }
}

// ---------------- gather aggregation: agg[n] = mean of x[src] -------------------
__global__ void agg_kernel(const float* __restrict__ xext, int in_sel, int g) {
    int warp = (blockIdx.x * blockDim.x + threadIdx.x) >> 5;
    int lane = threadIdx.x & 31;
    if (warp >= N_NODES) return;
    const float* xp = (in_sel < 0) ? xext : g_xbuf[in_sel][g];
    const float4* x = (const float4*)xp;
    const int* offs = g_offs + g * (N_NODES + 1);
    const int* csr = g_csr + g * N_EDGES;
    int s = offs[warp], e = offs[warp + 1];
    float4 acc = make_float4(0.f, 0.f, 0.f, 0.f);
    float4 acc2 = make_float4(0.f, 0.f, 0.f, 0.f);
    int j = s;
    for (; j + 1 < e; j += 2) {
        int s0 = csr[j], s1 = csr[j + 1];
        float4 t0 = x[s0 * 32 + lane];
        float4 t1 = x[s1 * 32 + lane];
        acc.x += t0.x; acc.y += t0.y; acc.z += t0.z; acc.w += t0.w;
        acc2.x += t1.x; acc2.y += t1.y; acc2.z += t1.z; acc2.w += t1.w;
    }
    if (j < e) {
        float4 t = x[csr[j] * 32 + lane];
        acc.x += t.x; acc.y += t.y; acc.z += t.z; acc.w += t.w;
    }
    acc.x += acc2.x; acc.y += acc2.y; acc.z += acc2.z; acc.w += acc2.w;
    int d = e - s; if (d < 1) d = 1;
    float inv = 1.0f / (float)d;
    acc.x *= inv; acc.y *= inv; acc.z *= inv; acc.w *= inv;
    ((float4*)g_agg[g])[warp * 32 + lane] = acc;
}

// ---------------- bf16x3 mma.sync GEMM -------------------------------------------
#define SW_ST 264
#define SA_ST 40
#define W_PLANE (128 * SW_ST * 2)            // bytes per W plane
#define A_PLANE (128 * SA_ST * 2)            // bytes per A plane
#define A_BASE  (2 * W_PLANE)
#define A_BUF   (2 * A_PLANE)                // hi + lo
#define EX_BASE (A_BASE + 2 * A_BUF)
#define GSMEM   (EX_BASE + 1024)

__device__ __forceinline__ void mma_bf16(float c[4], const uint32_t a[4],
                                         uint32_t b0, uint32_t b1) {
    asm volatile(
        "mma.sync.aligned.m16n8k16.row.col.f32.bf16.bf16.f32 "
        "{%0,%1,%2,%3},{%4,%5,%6,%7},{%8,%9},{%0,%1,%2,%3};"
        : "+f"(c[0]), "+f"(c[1]), "+f"(c[2]), "+f"(c[3])
        : "r"(a[0]), "r"(a[1]), "r"(a[2]), "r"(a[3]), "r"(b0), "r"(b1));
}

__global__ void __launch_bounds__(256)
gemm_kernel(const float* __restrict__ xext,
            const float* __restrict__ bl,
            const float* __restrict__ gam, const float* __restrict__ bet,
            const float* __restrict__ mean, const float* __restrict__ var,
            int layer, int in_sel, int out_sel, int g) {
    const float* x = (in_sel < 0) ? xext : g_xbuf[in_sel][g];
    const float* agg = g_agg[g];
    float* outp = g_xbuf[out_sel][g];

    extern __shared__ __align__(16) char sm[];
    char* sW0 = sm;                 // W b0 plane [128 n][264 k] bf16
    char* sW1 = sm + W_PLANE;       // W b1 plane
    float* ssc = (float*)(sm + EX_BASE);
    float* ssh = ssc + 128;

    int tid = threadIdx.x;
    int lane = tid & 31, wid = tid >> 5;
    int gp = lane >> 2, tig = lane & 3;
    int warp_m = (wid & 3) * 32;
    int warp_n = (wid >> 2) * 64;
    int row0 = blockIdx.x * 128;

    if (tid < 128) {
        float s = gam[tid] * rsqrtf(var[tid] + EPSBN);
        ssc[tid] = s;
        ssh[tid] = (bl[tid] - mean[tid]) * s + bet[tid];
    }

    {
        const uint4* w0 = (const uint4*)&g_wb[layer][0][0][0];
        const uint4* w1 = (const uint4*)&g_wb[layer][1][0][0];
        #pragma unroll
        for (int t = 0; t < 16; t++) {
            int i = tid + t * 256;
            int n = i >> 5, c16 = i & 31;
            *(uint4*)(sW0 + n * (SW_ST * 2) + c16 * 16) = w0[i];
            *(uint4*)(sW1 + n * (SW_ST * 2) + c16 * 16) = w1[i];
        }
    }

    float4 stage[4];
    auto ldg_chunk = [&](int c) {
        const float* src = (c < 4) ? agg : x;
        int coff = (c & 3) * 32;
        #pragma unroll
        for (int t = 0; t < 4; t++) {
            int i = tid + t * 256;
            int r = i >> 3, c4 = i & 7;
            float4 v = make_float4(0.f, 0.f, 0.f, 0.f);
            int row = row0 + r;
            if (row < N_NODES) v = *(const float4*)(src + row * 128 + coff + c4 * 4);
            stage[t] = v;
        }
    };
    auto sts_chunk = [&](int buf) {
        char* hi = sm + A_BASE + buf * A_BUF;
        char* lo = hi + A_PLANE;
        #pragma unroll
        for (int t = 0; t < 4; t++) {
            int i = tid + t * 256;
            int r = i >> 3, c4 = i & 7;
            float4 v = stage[t];
            uint32_t h01 = pack_bf2(v.x, v.y);
            uint32_t h23 = pack_bf2(v.z, v.w);
            uint32_t l01 = pack_bf2(v.x - bf_hi_part(v.x), v.y - bf_hi_part(v.y));
            uint32_t l23 = pack_bf2(v.z - bf_hi_part(v.z), v.w - bf_hi_part(v.w));
            uint32_t off = r * (SA_ST * 2) + c4 * 8;
            *(uint2*)(hi + off) = make_uint2(h01, h23);
            *(uint2*)(lo + off) = make_uint2(l01, l23);
        }
    };

    ldg_chunk(0);
    sts_chunk(0);
    __syncthreads();

    float acc[2][8][4];
    #pragma unroll
    for (int mt = 0; mt < 2; mt++)
        #pragma unroll
        for (int n8 = 0; n8 < 8; n8++)
            #pragma unroll
            for (int j = 0; j < 4; j++) acc[mt][n8][j] = 0.f;

    for (int c = 0; c < 8; c++) {
        if (c + 1 < 8) ldg_chunk(c + 1);
        int buf = c & 1;
        const char* Ahi = sm + A_BASE + buf * A_BUF;
        const char* Alo = Ahi + A_PLANE;
        #pragma unroll
        for (int k16 = 0; k16 < 2; k16++) {
            int kloc = k16 * 16 + tig * 2;
            uint32_t ah[2][4], al[2][4];
            #pragma unroll
            for (int mt = 0; mt < 2; mt++) {
                int r = warp_m + mt * 16 + gp;
                uint32_t o00 = r * (SA_ST * 2) + kloc * 2;
                uint32_t o10 = o00 + 8 * (SA_ST * 2);
                ah[mt][0] = *(const uint32_t*)(Ahi + o00);
                ah[mt][1] = *(const uint32_t*)(Ahi + o10);
                ah[mt][2] = *(const uint32_t*)(Ahi + o00 + 16);
                ah[mt][3] = *(const uint32_t*)(Ahi + o10 + 16);
                al[mt][0] = *(const uint32_t*)(Alo + o00);
                al[mt][1] = *(const uint32_t*)(Alo + o10);
                al[mt][2] = *(const uint32_t*)(Alo + o00 + 16);
                al[mt][3] = *(const uint32_t*)(Alo + o10 + 16);
            }
            int kg = c * 32 + k16 * 16 + tig * 2;
            #pragma unroll
            for (int n8 = 0; n8 < 8; n8++) {
                int n = warp_n + n8 * 8 + gp;
                uint32_t wo = n * (SW_ST * 2) + kg * 2;
                uint32_t bh0 = *(const uint32_t*)(sW0 + wo);
                uint32_t bh1 = *(const uint32_t*)(sW0 + wo + 16);
                uint32_t bl0 = *(const uint32_t*)(sW1 + wo);
                uint32_t bl1 = *(const uint32_t*)(sW1 + wo + 16);
                #pragma unroll
                for (int mt = 0; mt < 2; mt++) {
                    mma_bf16(acc[mt][n8], ah[mt], bh0, bh1);
                    mma_bf16(acc[mt][n8], al[mt], bh0, bh1);
                    mma_bf16(acc[mt][n8], ah[mt], bl0, bl1);
                }
            }
        }
        __syncthreads();
        if (c + 1 < 8) {
            sts_chunk(buf ^ 1);
            __syncthreads();
        }
    }

    #pragma unroll
    for (int mt = 0; mt < 2; mt++) {
        int ra = row0 + warp_m + mt * 16 + gp;
        int rb = ra + 8;
        #pragma unroll
        for (int n8 = 0; n8 < 8; n8++) {
            int col = warp_n + n8 * 8 + 2 * tig;
            float s0 = ssc[col], s1 = ssc[col + 1];
            float h0 = ssh[col], h1 = ssh[col + 1];
            if (ra < N_NODES) {
                float2 o;
                o.x = fmaxf(acc[mt][n8][0] * s0 + h0, 0.f);
                o.y = fmaxf(acc[mt][n8][1] * s1 + h1, 0.f);
                *(float2*)&outp[ra * 128 + col] = o;
            }
            if (rb < N_NODES) {
                float2 o;
                o.x = fmaxf(acc[mt][n8][2] * s0 + h0, 0.f);
                o.y = fmaxf(acc[mt][n8][3] * s1 + h1, 0.f);
                *(float2*)&outp[rb * 128 + col] = o;
            }
        }
    }
}

// ---------------- global add pool ------------------------------------------------
__global__ void pool_kernel(const int* __restrict__ batch, int in_sel, int g) {
    int warp = (blockIdx.x * blockDim.x + threadIdx.x) >> 5;
    int lane = threadIdx.x & 31;
    if (warp >= N_NODES) return;
    const float* xf = g_xbuf[in_sel][g];
    int b = batch[warp];
    float4 v = ((const float4*)xf)[warp * 32 + lane];
    float* p = &g_pool[g][b * 128 + lane * 4];
    atomicAdd(p + 0, v.x);
    atomicAdd(p + 1, v.y);
    atomicAdd(p + 2, v.z);
    atomicAdd(p + 3, v.w);
}

// ---------------- final MLP: [B,384]@[384,128] -> relu -> @[128,1] ---------------
__global__ void __launch_bounds__(128)
mlp_kernel(const int* __restrict__ rel, const float* __restrict__ kge,
           const float* __restrict__ W1, const float* __restrict__ b1,
           const float* __restrict__ W2, const float* __restrict__ b2,
           float* __restrict__ out) {
    __shared__ float zsm[8][384];
    __shared__ float red[8][4];
    int tid = threadIdx.x;
    int b0 = blockIdx.x * 8;
    #pragma unroll
    for (int j = 0; j < 8; j++) {
        int b = b0 + j;
        zsm[j][tid]       = g_pool[0][b * 128 + tid];
        zsm[j][128 + tid] = g_pool[1][b * 128 + tid];
        zsm[j][256 + tid] = kge[rel[b] * 128 + tid];
    }
    __syncthreads();
    float acc[8];
    float bias = b1[tid];
    #pragma unroll
    for (int j = 0; j < 8; j++) acc[j] = bias;
    for (int k = 0; k < 384; k++) {
        float w = W1[k * 128 + tid];
        #pragma unroll
        for (int j = 0; j < 8; j++) acc[j] += zsm[j][k] * w;
    }
    float w2 = W2[tid];
    #pragma unroll
    for (int j = 0; j < 8; j++) {
        float h = fmaxf(acc[j], 0.f) * w2;
        #pragma unroll
        for (int o = 16; o > 0; o >>= 1) h += __shfl_down_sync(0xffffffffu, h, o);
        if ((tid & 31) == 0) red[j][tid >> 5] = h;
    }
    __syncthreads();
    if (tid < 8)
        out[b0 + tid] = red[tid][0] + red[tid][1] + red[tid][2] + red[tid][3] + b2[0];
}

// ---------------- host launcher ---------------------------------------------------
extern "C" void kernel_launch(void* const* d_in, const int* in_sizes, int n_in,
                              void* d_out, int out_size) {
    int ix1 = 0, ie1, ib1, ix2, ie2, ib2;
    if (in_sizes[1] == 2 * N_EDGES) {           // reference-signature order
        ie1 = 1; ib1 = 2; ix2 = 3; ie2 = 4; ib2 = 5;
    } else {                                    // setup_inputs dict order
        ix2 = 1; ie1 = 2; ie2 = 3; ib1 = 4; ib2 = 5;
    }
    const float* x1     = (const float*)d_in[ix1];
    const float* x2     = (const float*)d_in[ix2];
    const int*   e1     = (const int*)d_in[ie1];
    const int*   e2     = (const int*)d_in[ie2];
    const int*   batch1 = (const int*)d_in[ib1];
    const int*   batch2 = (const int*)d_in[ib2];
    const int*   rel    = (const int*)d_in[6];
    const float* Wl     = (const float*)d_in[7];
    const float* bl     = (const float*)d_in[8];
    const float* Wr     = (const float*)d_in[9];
    const float* gam    = (const float*)d_in[10];
    const float* bet    = (const float*)d_in[11];
    const float* mean   = (const float*)d_in[12];
    const float* var    = (const float*)d_in[13];
    const float* kge    = (const float*)d_in[14];
    const float* W1     = (const float*)d_in[15];
    const float* b1     = (const float*)d_in[16];
    const float* W2     = (const float*)d_in[17];
    const float* b2     = (const float*)d_in[18];
    float* out = (float*)d_out;

    static cudaStream_t sG[2] = {nullptr, nullptr};
    static cudaEvent_t evF = nullptr, evJ[2] = {nullptr, nullptr};
    static int init_done = 0;
    if (!init_done) {
        cudaFuncSetAttribute(gemm_kernel, cudaFuncAttributeMaxDynamicSharedMemorySize,
                             GSMEM);
        cudaStreamCreateWithFlags(&sG[0], cudaStreamNonBlocking);
        cudaStreamCreateWithFlags(&sG[1], cudaStreamNonBlocking);
        cudaEventCreateWithFlags(&evF, cudaEventDisableTiming);
        cudaEventCreateWithFlags(&evJ[0], cudaEventDisableTiming);
        cudaEventCreateWithFlags(&evJ[1], cudaEventDisableTiming);
        init_done = 1;
    }

    // prolog on capture (default) stream
    zero_kernel<<<256, 256>>>();
    wsplit_kernel<<<(L_IT * 128 * 256 + 255) / 256, 256>>>(Wl, Wr);

    // fork the two independent graph pipelines onto their own streams
    cudaEventRecord(evF, 0);
    cudaStreamWaitEvent(sG[0], evF, 0);
    cudaStreamWaitEvent(sG[1], evF, 0);

    const int* eg[2]     = {e1, e2};
    const float* xg[2]   = {x1, x2};
    const int* batchg[2] = {batch1, batch2};

    int gEb = (N_EDGES + 255) / 256;
    int gWb = (N_NODES + 7) / 8;
    int gGb = (N_NODES + 127) / 128;

    int final_sel = 0;
    for (int g = 0; g < 2; g++) {
        cudaStream_t st = sG[g];
        hist_kernel<<<gEb, 256, 0, st>>>(eg[g], g);
        scan1_kernel<<<SCAN_NB, 1024, 0, st>>>(g);
        scan2_kernel<<<1, 32, 0, st>>>(g);
        scan3_kernel<<<SCAN_NB, 1024, 0, st>>>(g);
        scatter_kernel<<<gEb, 256, 0, st>>>(eg[g], g);

        int in_sel = -1, out_sel = 0;
        for (int l = 0; l < L_IT; l++) {
            agg_kernel<<<gWb, 256, 0, st>>>(xg[g], in_sel, g);
            gemm_kernel<<<gGb, 256, GSMEM, st>>>(xg[g],
                                                 bl + l * DIM,
                                                 gam + l * DIM, bet + l * DIM,
                                                 mean + l * DIM, var + l * DIM,
                                                 l, in_sel, out_sel, g);
            in_sel = out_sel;
            out_sel ^= 1;
        }
        final_sel = in_sel;
        pool_kernel<<<gWb, 256, 0, st>>>(batchg[g], in_sel, g);
        cudaEventRecord(evJ[g], st);
    }

    // join and run the final MLP on the capture stream
    cudaStreamWaitEvent(0, evJ[0], 0);
    cudaStreamWaitEvent(0, evJ[1], 0);
    mlp_kernel<<<B_GR / 8, 128>>>(rel, kge, W1, b1, W2, b2, out);
    (void)n_in; (void)out_size; (void)final_sel;
}